// round 11
// baseline (speedup 1.0000x reference)
#include <cuda_runtime.h>
#include <cuda_bf16.h>
#include <cstdint>

#define NNODES 100000
#define NEDGES 500000
#define DIM 128
#define NHEADS 4
#define NTILES ((NNODES + 127) / 128)      // 782
#define SCAN_B ((NNODES + 255) / 256)      // 391

// ---------------- scratch ----------------
__device__ float  g_h[NNODES * DIM];           // 51.2 MB
__device__ float  g_h32[NNODES * 32];          // 12.8 MB, L2-resident gather table
__device__ float  g_asrc[NNODES * NHEADS];
__device__ float  g_adst[NNODES * NHEADS];
__device__ float  g_exp[NEDGES * NHEADS];      // unnormalized exp(logit), 8 MB
__device__ float  g_va[8 * DIM];               // wa @ W (4 src rows, 4 dst rows)
__device__ float  g_vc[8];                     // b·wa (+ba for dst part)
__device__ float  g_sum[NHEADS];
__device__ float  g_inv[NHEADS];
// pre-split, pre-swizzled B operand (144 rows x 128 cols bf16, hi+lo) + fused bias
__device__ __nv_bfloat16 g_Bhi[144 * 128];
__device__ __nv_bfloat16 g_Blo[144 * 128];
__device__ float  g_bias[144];
// counting-sort scratch
__device__ int    g_cnt[NNODES];
__device__ int    g_cnt2[NNODES];
__device__ int    g_base[NNODES + 1];
__device__ int    g_part[SCAN_B];
__device__ int    g_poff[SCAN_B];
__device__ int    g_esrc[NEDGES];
__device__ float4 g_ea[NEDGES];                // unnormalized exp per sorted slot

// ---------------- helpers ----------------
__device__ __forceinline__ uint32_t smaddr(const void* p) {
    return (uint32_t)__cvta_generic_to_shared(p);
}
// packed split: v0,v1 -> bf16x2 hi pair + bf16x2 lo pair
__device__ __forceinline__ void split2(float v0, float v1, uint32_t& hp, uint32_t& lp) {
    asm("cvt.rn.bf16x2.f32 %0, %1, %2;" : "=r"(hp) : "f"(v1), "f"(v0));
    float h0 = __uint_as_float(hp << 16);
    float h1 = __uint_as_float(hp & 0xffff0000u);
    asm("cvt.rn.bf16x2.f32 %0, %1, %2;" : "=r"(lp) : "f"(v1 - h1), "f"(v0 - h0));
}
// swizzled element offset within a [rows][128] bf16 tile (16B chunk xor swizzle)
__device__ __forceinline__ int swz(int row, int ch) {
    return row * 128 + ((ch ^ (row & 7)) << 3);
}

#define LDSM4(r0, r1, r2, r3, addr) \
    asm volatile("ldmatrix.sync.aligned.m8n8.x4.shared.b16 {%0,%1,%2,%3}, [%4];" \
                 : "=r"(r0), "=r"(r1), "=r"(r2), "=r"(r3) : "r"(addr))
#define MMA16816(d, a, b0, b1) \
    asm volatile("mma.sync.aligned.m16n8k16.row.col.f32.bf16.bf16.f32 " \
                 "{%0,%1,%2,%3}, {%4,%5,%6,%7}, {%8,%9}, {%0,%1,%2,%3};" \
                 : "+f"(d[0]), "+f"(d[1]), "+f"(d[2]), "+f"(d[3]) \
                 : "r"(a[0]), "r"(a[1]), "r"(a[2]), "r"(a[3]), "r"(b0), "r"(b1))

// ---------------- K0: zero counters + va (fused) ----------------
__global__ void prep_kernel(const float* __restrict__ W,
                            const float* __restrict__ b,
                            const float* __restrict__ Wa,
                            const float* __restrict__ ba) {
    int i = blockIdx.x * blockDim.x + threadIdx.x;
    if (i < NNODES) { g_cnt[i] = 0; g_cnt2[i] = 0; }
    if (i < NHEADS) g_sum[i] = 0.0f;
    if (blockIdx.x == 0) {      // 1024 threads: va = wa @ W
        int t = threadIdx.x;
        int j = t >> 7, ii = t & 127;
        int head = j & 3, part = j >> 2;
        const float* war = Wa + head * 2 * DIM + part * DIM;
        float s = 0.f;
        for (int k = 0; k < DIM; k++) s += war[k] * W[k * DIM + ii];
        g_va[j * DIM + ii] = s;
        if (t < 8) {
            int hh = t & 3, pp = t >> 2;
            const float* wr = Wa + hh * 2 * DIM + pp * DIM;
            float c = 0.f;
            for (int k = 0; k < DIM; k++) c += b[k] * wr[k];
            if (pp) c += ba[hh];
            g_vc[t] = c;
        }
    }
}

// ---------------- K0c: pre-split + pre-swizzle B, fuse bias ----------------
__global__ void splitB_kernel(const float* __restrict__ W,
                              const float* __restrict__ b) {
    int idx = blockIdx.x * blockDim.x + threadIdx.x;   // 144*16 items
    if (idx >= 144 * 16) return;
    int row = idx >> 4, ch = idx & 15;
    float v[8];
    if (row < 128) {
        const float4* p = (const float4*)(W + row * 128 + ch * 8);
        float4 a = p[0], c = p[1];
        v[0] = a.x; v[1] = a.y; v[2] = a.z; v[3] = a.w;
        v[4] = c.x; v[5] = c.y; v[6] = c.z; v[7] = c.w;
    } else if (row < 136) {
        const float4* p = (const float4*)(g_va + (row - 128) * 128 + ch * 8);
        float4 a = p[0], c = p[1];
        v[0] = a.x; v[1] = a.y; v[2] = a.z; v[3] = a.w;
        v[4] = c.x; v[5] = c.y; v[6] = c.z; v[7] = c.w;
    } else {
#pragma unroll
        for (int i = 0; i < 8; i++) v[i] = 0.f;
    }
    uint32_t uh[4], ul[4];
#pragma unroll
    for (int i = 0; i < 4; i++) split2(v[2 * i], v[2 * i + 1], uh[i], ul[i]);
    int off = swz(row, ch);
    *(uint4*)(g_Bhi + off) = make_uint4(uh[0], uh[1], uh[2], uh[3]);
    *(uint4*)(g_Blo + off) = make_uint4(ul[0], ul[1], ul[2], ul[3]);
    if (idx < 144)
        g_bias[idx] = (idx < 128) ? b[idx] : (idx < 136 ? g_vc[idx - 128] : 0.f);
}

// ---------------- K1: persistent split-bf16 tensor-core GEMM ----------------
__global__ void __launch_bounds__(256, 2)
gemm_kernel(const float* __restrict__ feat) {
    extern __shared__ char smraw[];
    __nv_bfloat16* Ahi = (__nv_bfloat16*)smraw;          // 128*128 (32KB)
    __nv_bfloat16* Alo = Ahi + 128 * 128;                // 32KB
    __nv_bfloat16* Bhi = Alo + 128 * 128;                // 72*128 (18KB)
    __nv_bfloat16* Blo = Bhi + 72 * 128;                 // 18KB
    float* sbias = (float*)(Blo + 72 * 128);             // 72

    int tid = threadIdx.x;
    int ny = blockIdx.x & 1;
    int col_base = ny * 72;

    // ---- stage B once ----
    {
        const uint4* srcH = (const uint4*)(g_Bhi + col_base * 128);
        const uint4* srcL = (const uint4*)(g_Blo + col_base * 128);
        for (int i = tid; i < 72 * 128 / 8; i += 256) {
            ((uint4*)Bhi)[i] = srcH[i];
            ((uint4*)Blo)[i] = srcL[i];
        }
        for (int i = tid; i < 72; i += 256) sbias[i] = g_bias[col_base + i];
    }

    int warp = tid >> 5, lane = tid & 31;
    int tq = lane >> 2, tr = lane & 3;

    for (int tile = blockIdx.x >> 1; tile < NTILES; tile += gridDim.x >> 1) {
        int nb = tile * 128;

        // ---- stage A tile ----
        for (int idx = tid; idx < 128 * 16; idx += 256) {
            int row = idx >> 4, ch = idx & 15;
            int node = nb + row;
            float v[8];
            if (node < NNODES) {
                const float4* p = (const float4*)(feat + (size_t)node * 128 + ch * 8);
                float4 a = p[0], c = p[1];
                v[0] = a.x; v[1] = a.y; v[2] = a.z; v[3] = a.w;
                v[4] = c.x; v[5] = c.y; v[6] = c.z; v[7] = c.w;
            } else {
#pragma unroll
                for (int i = 0; i < 8; i++) v[i] = 0.f;
            }
            uint32_t uh[4], ul[4];
#pragma unroll
            for (int i = 0; i < 4; i++) split2(v[2 * i], v[2 * i + 1], uh[i], ul[i]);
            int off = swz(row, ch);
            *(uint4*)(Ahi + off) = make_uint4(uh[0], uh[1], uh[2], uh[3]);
            *(uint4*)(Alo + off) = make_uint4(ul[0], ul[1], ul[2], ul[3]);
        }
        __syncthreads();

        float acc[9][4];
#pragma unroll
        for (int nt = 0; nt < 9; nt++)
#pragma unroll
            for (int i = 0; i < 4; i++) acc[nt][i] = 0.f;

        for (int ks = 0; ks < 8; ks++) {
            uint32_t ah[4], al[4];
            {
                int row = warp * 16 + (lane & 15);
                int ch = ks * 2 + (lane >> 4);
                uint32_t ad = smaddr(Ahi + swz(row, ch));
                LDSM4(ah[0], ah[1], ah[2], ah[3], ad);
                uint32_t ad2 = smaddr(Alo + swz(row, ch));
                LDSM4(al[0], al[1], al[2], al[3], ad2);
            }
            int rowb_pair = (lane & 7) + ((lane >> 4) << 3);
            int chb = ks * 2 + ((lane >> 3) & 1);

            uint32_t bh[4][4], bl[4][4], bh8[2], bl8[2];
#pragma unroll
            for (int np = 0; np < 4; np++) {
                int rb = np * 16 + rowb_pair;
                uint32_t bd = smaddr(Bhi + swz(rb, chb));
                LDSM4(bh[np][0], bh[np][1], bh[np][2], bh[np][3], bd);
                uint32_t bd2 = smaddr(Blo + swz(rb, chb));
                LDSM4(bl[np][0], bl[np][1], bl[np][2], bl[np][3], bd2);
            }
            {
                int rb = 64 + (lane & 7);
                const __nv_bfloat16* Bt = (lane & 16) ? Blo : Bhi;
                uint32_t bd = smaddr(Bt + swz(rb, chb));
                LDSM4(bh8[0], bh8[1], bl8[0], bl8[1], bd);
            }

#pragma unroll
            for (int np = 0; np < 4; np++) {
                MMA16816(acc[2 * np],     ah, bh[np][0], bh[np][1]);
                MMA16816(acc[2 * np + 1], ah, bh[np][2], bh[np][3]);
            }
            MMA16816(acc[8], ah, bh8[0], bh8[1]);
#pragma unroll
            for (int np = 0; np < 4; np++) {
                MMA16816(acc[2 * np],     ah, bl[np][0], bl[np][1]);
                MMA16816(acc[2 * np + 1], ah, bl[np][2], bl[np][3]);
            }
            MMA16816(acc[8], ah, bl8[0], bl8[1]);
#pragma unroll
            for (int np = 0; np < 4; np++) {
                MMA16816(acc[2 * np],     al, bh[np][0], bh[np][1]);
                MMA16816(acc[2 * np + 1], al, bh[np][2], bh[np][3]);
            }
            MMA16816(acc[8], al, bh8[0], bh8[1]);
        }

        // ---- epilogue ----
#pragma unroll
        for (int nt = 0; nt < 9; nt++) {
            int col = col_base + nt * 8 + tr * 2;
            if (col >= 136) continue;
            float b0 = sbias[nt * 8 + tr * 2], b1 = sbias[nt * 8 + tr * 2 + 1];
#pragma unroll
            for (int half = 0; half < 2; half++) {
                int node = nb + warp * 16 + tq + half * 8;
                if (node >= NNODES) continue;
                float v0 = acc[nt][half * 2] + b0;
                float v1 = acc[nt][half * 2 + 1] + b1;
                if (col < 128) {
                    float2 o; o.x = v0; o.y = v1;
                    *(float2*)(g_h + (size_t)node * DIM + col) = o;
                    if (col < 32)      // compact L2-resident gather table
                        *(float2*)(g_h32 + (size_t)node * 32 + col) = o;
                } else {
                    int j = col - 128;        // even: 0,2,4,6
                    if (j < 4) {
                        g_asrc[node * NHEADS + j] = v0;
                        g_asrc[node * NHEADS + j + 1] = v1;
                    } else {
                        g_adst[node * NHEADS + j - 4] = v0;
                        g_adst[node * NHEADS + j - 3] = v1;
                    }
                }
            }
        }
        __syncthreads();
    }
}

// ---------------- K2: exp(logits) + dst histogram + sum ----------------
__global__ void logits_hist_kernel(const int* __restrict__ ei) {
    const int* src = ei;
    const int* dst = ei + NEDGES;
    float s0 = 0.f, s1 = 0.f, s2 = 0.f, s3 = 0.f;
    int stride = gridDim.x * blockDim.x;
    for (int e = blockIdx.x * blockDim.x + threadIdx.x; e < NEDGES; e += stride) {
        int s = src[e], d = dst[e];
        atomicAdd(&g_cnt[d], 1);
        float4 as = *(const float4*)(g_asrc + (size_t)s * 4);
        float4 ad = *(const float4*)(g_adst + (size_t)d * 4);
        float4 l;
        l.x = __expf(as.x + ad.x); l.y = __expf(as.y + ad.y);
        l.z = __expf(as.z + ad.z); l.w = __expf(as.w + ad.w);
        *(float4*)(g_exp + (size_t)e * 4) = l;
        s0 += l.x; s1 += l.y; s2 += l.z; s3 += l.w;
    }
    __shared__ float red[4][8];
    int lane = threadIdx.x & 31, w = threadIdx.x >> 5;
#pragma unroll
    for (int o = 16; o; o >>= 1) {
        s0 += __shfl_down_sync(0xffffffffu, s0, o);
        s1 += __shfl_down_sync(0xffffffffu, s1, o);
        s2 += __shfl_down_sync(0xffffffffu, s2, o);
        s3 += __shfl_down_sync(0xffffffffu, s3, o);
    }
    if (lane == 0) { red[0][w] = s0; red[1][w] = s1; red[2][w] = s2; red[3][w] = s3; }
    __syncthreads();
    if (threadIdx.x < 4) {
        float ss = 0.f;
#pragma unroll
        for (int i = 0; i < 8; i++) ss += red[threadIdx.x][i];
        atomicAdd(&g_sum[threadIdx.x], ss);
    }
}

// ---------------- K4a/b: two-level exclusive scan ----------------
__global__ void scan1_kernel() {
    __shared__ int sd[256];
    int t = threadIdx.x;
    int idx = blockIdx.x * 256 + t;
    int v = (idx < NNODES) ? g_cnt[idx] : 0;
    sd[t] = v; __syncthreads();
#pragma unroll
    for (int off = 1; off < 256; off <<= 1) {
        int x = (t >= off) ? sd[t - off] : 0;
        __syncthreads();
        sd[t] += x;
        __syncthreads();
    }
    if (idx < NNODES) g_base[idx] = sd[t] - v;
    if (t == 255) g_part[blockIdx.x] = sd[255];
}
__global__ void scan2_kernel() {
    if (threadIdx.x < NHEADS) g_inv[threadIdx.x] = 1.0f / g_sum[threadIdx.x];
    __shared__ int sd[512];
    int t = threadIdx.x;
    int v = (t < SCAN_B) ? g_part[t] : 0;
    sd[t] = v; __syncthreads();
#pragma unroll
    for (int off = 1; off < 512; off <<= 1) {
        int x = (t >= off) ? sd[t - off] : 0;
        __syncthreads();
        sd[t] += x;
        __syncthreads();
    }
    if (t < SCAN_B) g_poff[t] = sd[t] - v;
    if (t == SCAN_B - 1) g_base[NNODES] = NEDGES - (sd[t] - v);
}

// ---------------- K5: place edges into dst-sorted order (pure permutation) ----
__global__ void place_kernel(const int* __restrict__ ei) {
    const int* src = ei;
    const int* dst = ei + NEDGES;
    int stride = gridDim.x * blockDim.x;
    for (int e = blockIdx.x * blockDim.x + threadIdx.x; e < NEDGES; e += stride) {
        int d = dst[e];
        int pos = g_base[d] + g_poff[d >> 8] + atomicAdd(&g_cnt2[d], 1);
        g_esrc[pos] = src[e];
        g_ea[pos] = *(const float4*)(g_exp + (size_t)e * 4);
    }
}

// ---------------- K6: warp-per-dst aggregation, out = h + inv*agg ----------------
__global__ void agg_kernel(float* __restrict__ out) {
    int lane = threadIdx.x & 31;
    int w = (blockIdx.x * blockDim.x + threadIdx.x) >> 5;
    int nw = (gridDim.x * blockDim.x) >> 5;
    float i0 = g_inv[0], i1 = g_inv[1], i2 = g_inv[2], i3 = g_inv[3];
    for (int d = w; d < NNODES; d += nw) {
        int beg = g_base[d] + g_poff[d >> 8];
        int end = g_base[d + 1] + g_poff[(d + 1) >> 8];
        float a0 = 0.f, a1 = 0.f, a2 = 0.f, a3 = 0.f;
        int p = beg;
        for (; p + 4 <= end; p += 4) {
            int s0 = g_esrc[p], s1 = g_esrc[p + 1], s2 = g_esrc[p + 2], s3 = g_esrc[p + 3];
            float4 w0 = g_ea[p], w1 = g_ea[p + 1], w2 = g_ea[p + 2], w3 = g_ea[p + 3];
            float v0 = g_h32[(size_t)s0 * 32 + lane];
            float v1 = g_h32[(size_t)s1 * 32 + lane];
            float v2 = g_h32[(size_t)s2 * 32 + lane];
            float v3 = g_h32[(size_t)s3 * 32 + lane];
            a0 = fmaf(w0.x, v0, fmaf(w1.x, v1, fmaf(w2.x, v2, fmaf(w3.x, v3, a0))));
            a1 = fmaf(w0.y, v0, fmaf(w1.y, v1, fmaf(w2.y, v2, fmaf(w3.y, v3, a1))));
            a2 = fmaf(w0.z, v0, fmaf(w1.z, v1, fmaf(w2.z, v2, fmaf(w3.z, v3, a2))));
            a3 = fmaf(w0.w, v0, fmaf(w1.w, v1, fmaf(w2.w, v2, fmaf(w3.w, v3, a3))));
        }
        for (; p < end; p++) {
            int s = g_esrc[p];
            float4 a = g_ea[p];
            float sv = g_h32[(size_t)s * 32 + lane];
            a0 = fmaf(a.x, sv, a0);
            a1 = fmaf(a.y, sv, a1);
            a2 = fmaf(a.z, sv, a2);
            a3 = fmaf(a.w, sv, a3);
        }
        const float* hr = g_h + (size_t)d * DIM;
        float* o = out + (size_t)d * DIM;
        o[lane]      = hr[lane]      + a0 * i0;
        o[32 + lane] = hr[32 + lane] + a1 * i1;
        o[64 + lane] = hr[64 + lane] + a2 * i2;
        o[96 + lane] = hr[96 + lane] + a3 * i3;
    }
}

// ---------------- launch ----------------
extern "C" void kernel_launch(void* const* d_in, const int* in_sizes, int n_in,
                              void* d_out, int out_size) {
    const float* feat = (const float*)d_in[0];
    const int*   ei   = (const int*)d_in[1];
    const float* Wlin = (const float*)d_in[2];
    const float* blin = (const float*)d_in[3];
    const float* Watt = (const float*)d_in[4];
    const float* batt = (const float*)d_in[5];
    float* out = (float*)d_out;

    prep_kernel<<<(NNODES + 1023) / 1024, 1024>>>(Wlin, blin, Watt, batt);
    splitB_kernel<<<(144 * 16 + 255) / 256, 256>>>(Wlin, blin);

    size_t smem = (size_t)(2 * 128 * 128 + 2 * 72 * 128) * sizeof(__nv_bfloat16)
                + 72 * sizeof(float);
    cudaFuncSetAttribute(gemm_kernel, cudaFuncAttributeMaxDynamicSharedMemorySize, (int)smem);
    gemm_kernel<<<296, 256, smem>>>(feat);

    logits_hist_kernel<<<1184, 256>>>(ei);
    scan1_kernel<<<SCAN_B, 256>>>();
    scan2_kernel<<<1, 512>>>();
    place_kernel<<<1184, 256>>>(ei);
    agg_kernel<<<1480, 256>>>(out);
}

// round 13
// speedup vs baseline: 1.0422x; 1.0422x over previous
#include <cuda_runtime.h>
#include <cuda_bf16.h>
#include <cstdint>

#define NNODES 100000
#define NEDGES 500000
#define DIM 128
#define NHEADS 4
#define NTILES ((NNODES + 127) / 128)      // 782
#define SCAN_B ((NNODES + 255) / 256)      // 391

// ---------------- scratch ----------------
__device__ float  g_h[NNODES * DIM];           // 51.2 MB (L2-resident)
__device__ float  g_asrc[NNODES * NHEADS];
__device__ float  g_adst[NNODES * NHEADS];
__device__ float  g_exp[NEDGES * NHEADS];      // unnormalized exp(logit), 8 MB
__device__ float  g_va[8 * DIM];               // wa @ W (4 src rows, 4 dst rows)
__device__ float  g_vc[8];                     // b·wa (+ba for dst part)
__device__ float  g_sum[NHEADS];
__device__ float  g_inv[NHEADS];
// pre-split, pre-swizzled B operand (144 rows x 128 cols bf16, hi+lo) + fused bias
__device__ __nv_bfloat16 g_Bhi[144 * 128];
__device__ __nv_bfloat16 g_Blo[144 * 128];
__device__ float  g_bias[144];
// counting-sort scratch
__device__ int    g_cnt[NNODES];
__device__ int    g_cnt2[NNODES];
__device__ int    g_base[NNODES + 1];
__device__ int    g_part[SCAN_B];
__device__ int    g_poff[SCAN_B];
__device__ int    g_esrc[NEDGES];
__device__ float4 g_ea[NEDGES];                // unnormalized exp per sorted slot

// ---------------- helpers ----------------
__device__ __forceinline__ uint32_t smaddr(const void* p) {
    return (uint32_t)__cvta_generic_to_shared(p);
}
// packed split: v0,v1 -> bf16x2 hi pair + bf16x2 lo pair
__device__ __forceinline__ void split2(float v0, float v1, uint32_t& hp, uint32_t& lp) {
    asm("cvt.rn.bf16x2.f32 %0, %1, %2;" : "=r"(hp) : "f"(v1), "f"(v0));
    float h0 = __uint_as_float(hp << 16);
    float h1 = __uint_as_float(hp & 0xffff0000u);
    asm("cvt.rn.bf16x2.f32 %0, %1, %2;" : "=r"(lp) : "f"(v1 - h1), "f"(v0 - h0));
}
// swizzled element offset within a [rows][128] bf16 tile (16B chunk xor swizzle)
__device__ __forceinline__ int swz(int row, int ch) {
    return row * 128 + ((ch ^ (row & 7)) << 3);
}

#define LDSM4(r0, r1, r2, r3, addr) \
    asm volatile("ldmatrix.sync.aligned.m8n8.x4.shared.b16 {%0,%1,%2,%3}, [%4];" \
                 : "=r"(r0), "=r"(r1), "=r"(r2), "=r"(r3) : "r"(addr))
#define MMA16816(d, a, b0, b1) \
    asm volatile("mma.sync.aligned.m16n8k16.row.col.f32.bf16.bf16.f32 " \
                 "{%0,%1,%2,%3}, {%4,%5,%6,%7}, {%8,%9}, {%0,%1,%2,%3};" \
                 : "+f"(d[0]), "+f"(d[1]), "+f"(d[2]), "+f"(d[3]) \
                 : "r"(a[0]), "r"(a[1]), "r"(a[2]), "r"(a[3]), "r"(b0), "r"(b1))

// ---------------- K0: zero counters + va (fused) ----------------
__global__ void prep_kernel(const float* __restrict__ W,
                            const float* __restrict__ b,
                            const float* __restrict__ Wa,
                            const float* __restrict__ ba) {
    int i = blockIdx.x * blockDim.x + threadIdx.x;
    if (i < NNODES) { g_cnt[i] = 0; g_cnt2[i] = 0; }
    if (i < NHEADS) g_sum[i] = 0.0f;
    if (blockIdx.x == 0) {      // 1024 threads: va = wa @ W
        int t = threadIdx.x;
        int j = t >> 7, ii = t & 127;
        int head = j & 3, part = j >> 2;
        const float* war = Wa + head * 2 * DIM + part * DIM;
        float s = 0.f;
        for (int k = 0; k < DIM; k++) s += war[k] * W[k * DIM + ii];
        g_va[j * DIM + ii] = s;
        if (t < 8) {
            int hh = t & 3, pp = t >> 2;
            const float* wr = Wa + hh * 2 * DIM + pp * DIM;
            float c = 0.f;
            for (int k = 0; k < DIM; k++) c += b[k] * wr[k];
            if (pp) c += ba[hh];
            g_vc[t] = c;
        }
    }
}

// ---------------- K0c: pre-split + pre-swizzle B, fuse bias ----------------
__global__ void splitB_kernel(const float* __restrict__ W,
                              const float* __restrict__ b) {
    int idx = blockIdx.x * blockDim.x + threadIdx.x;   // 144*16 items
    if (idx >= 144 * 16) return;
    int row = idx >> 4, ch = idx & 15;
    float v[8];
    if (row < 128) {
        const float4* p = (const float4*)(W + row * 128 + ch * 8);
        float4 a = p[0], c = p[1];
        v[0] = a.x; v[1] = a.y; v[2] = a.z; v[3] = a.w;
        v[4] = c.x; v[5] = c.y; v[6] = c.z; v[7] = c.w;
    } else if (row < 136) {
        const float4* p = (const float4*)(g_va + (row - 128) * 128 + ch * 8);
        float4 a = p[0], c = p[1];
        v[0] = a.x; v[1] = a.y; v[2] = a.z; v[3] = a.w;
        v[4] = c.x; v[5] = c.y; v[6] = c.z; v[7] = c.w;
    } else {
#pragma unroll
        for (int i = 0; i < 8; i++) v[i] = 0.f;
    }
    uint32_t uh[4], ul[4];
#pragma unroll
    for (int i = 0; i < 4; i++) split2(v[2 * i], v[2 * i + 1], uh[i], ul[i]);
    int off = swz(row, ch);
    *(uint4*)(g_Bhi + off) = make_uint4(uh[0], uh[1], uh[2], uh[3]);
    *(uint4*)(g_Blo + off) = make_uint4(ul[0], ul[1], ul[2], ul[3]);
    if (idx < 144)
        g_bias[idx] = (idx < 128) ? b[idx] : (idx < 136 ? g_vc[idx - 128] : 0.f);
}

// ---------------- K1: persistent split-bf16 tensor-core GEMM (R10 proven) ----
__global__ void __launch_bounds__(256, 2)
gemm_kernel(const float* __restrict__ feat) {
    extern __shared__ char smraw[];
    __nv_bfloat16* Ahi = (__nv_bfloat16*)smraw;          // 128*128 (32KB)
    __nv_bfloat16* Alo = Ahi + 128 * 128;                // 32KB
    __nv_bfloat16* Bhi = Alo + 128 * 128;                // 72*128 (18KB)
    __nv_bfloat16* Blo = Bhi + 72 * 128;                 // 18KB
    float* sbias = (float*)(Blo + 72 * 128);             // 72

    int tid = threadIdx.x;
    int ny = blockIdx.x & 1;
    int col_base = ny * 72;

    // ---- stage B once ----
    {
        const uint4* srcH = (const uint4*)(g_Bhi + col_base * 128);
        const uint4* srcL = (const uint4*)(g_Blo + col_base * 128);
        for (int i = tid; i < 72 * 128 / 8; i += 256) {
            ((uint4*)Bhi)[i] = srcH[i];
            ((uint4*)Blo)[i] = srcL[i];
        }
        for (int i = tid; i < 72; i += 256) sbias[i] = g_bias[col_base + i];
    }

    int warp = tid >> 5, lane = tid & 31;
    int tq = lane >> 2, tr = lane & 3;

    for (int tile = blockIdx.x >> 1; tile < NTILES; tile += gridDim.x >> 1) {
        int nb = tile * 128;

        // ---- stage A tile ----
        for (int idx = tid; idx < 128 * 16; idx += 256) {
            int row = idx >> 4, ch = idx & 15;
            int node = nb + row;
            float v[8];
            if (node < NNODES) {
                const float4* p = (const float4*)(feat + (size_t)node * 128 + ch * 8);
                float4 a = p[0], c = p[1];
                v[0] = a.x; v[1] = a.y; v[2] = a.z; v[3] = a.w;
                v[4] = c.x; v[5] = c.y; v[6] = c.z; v[7] = c.w;
            } else {
#pragma unroll
                for (int i = 0; i < 8; i++) v[i] = 0.f;
            }
            uint32_t uh[4], ul[4];
#pragma unroll
            for (int i = 0; i < 4; i++) split2(v[2 * i], v[2 * i + 1], uh[i], ul[i]);
            int off = swz(row, ch);
            *(uint4*)(Ahi + off) = make_uint4(uh[0], uh[1], uh[2], uh[3]);
            *(uint4*)(Alo + off) = make_uint4(ul[0], ul[1], ul[2], ul[3]);
        }
        __syncthreads();

        float acc[9][4];
#pragma unroll
        for (int nt = 0; nt < 9; nt++)
#pragma unroll
            for (int i = 0; i < 4; i++) acc[nt][i] = 0.f;

        for (int ks = 0; ks < 8; ks++) {
            uint32_t ah[4], al[4];
            {
                int row = warp * 16 + (lane & 15);
                int ch = ks * 2 + (lane >> 4);
                uint32_t ad = smaddr(Ahi + swz(row, ch));
                LDSM4(ah[0], ah[1], ah[2], ah[3], ad);
                uint32_t ad2 = smaddr(Alo + swz(row, ch));
                LDSM4(al[0], al[1], al[2], al[3], ad2);
            }
            int rowb_pair = (lane & 7) + ((lane >> 4) << 3);
            int chb = ks * 2 + ((lane >> 3) & 1);

            uint32_t bh[4][4], bl[4][4], bh8[2], bl8[2];
#pragma unroll
            for (int np = 0; np < 4; np++) {
                int rb = np * 16 + rowb_pair;
                uint32_t bd = smaddr(Bhi + swz(rb, chb));
                LDSM4(bh[np][0], bh[np][1], bh[np][2], bh[np][3], bd);
                uint32_t bd2 = smaddr(Blo + swz(rb, chb));
                LDSM4(bl[np][0], bl[np][1], bl[np][2], bl[np][3], bd2);
            }
            {
                int rb = 64 + (lane & 7);
                const __nv_bfloat16* Bt = (lane & 16) ? Blo : Bhi;
                uint32_t bd = smaddr(Bt + swz(rb, chb));
                LDSM4(bh8[0], bh8[1], bl8[0], bl8[1], bd);
            }

#pragma unroll
            for (int np = 0; np < 4; np++) {
                MMA16816(acc[2 * np],     ah, bh[np][0], bh[np][1]);
                MMA16816(acc[2 * np + 1], ah, bh[np][2], bh[np][3]);
            }
            MMA16816(acc[8], ah, bh8[0], bh8[1]);
#pragma unroll
            for (int np = 0; np < 4; np++) {
                MMA16816(acc[2 * np],     ah, bl[np][0], bl[np][1]);
                MMA16816(acc[2 * np + 1], ah, bl[np][2], bl[np][3]);
            }
            MMA16816(acc[8], ah, bl8[0], bl8[1]);
#pragma unroll
            for (int np = 0; np < 4; np++) {
                MMA16816(acc[2 * np],     al, bh[np][0], bh[np][1]);
                MMA16816(acc[2 * np + 1], al, bh[np][2], bh[np][3]);
            }
            MMA16816(acc[8], al, bh8[0], bh8[1]);
        }

        // ---- epilogue ----
#pragma unroll
        for (int nt = 0; nt < 9; nt++) {
            int col = col_base + nt * 8 + tr * 2;
            if (col >= 136) continue;
            float b0 = sbias[nt * 8 + tr * 2], b1 = sbias[nt * 8 + tr * 2 + 1];
#pragma unroll
            for (int half = 0; half < 2; half++) {
                int node = nb + warp * 16 + tq + half * 8;
                if (node >= NNODES) continue;
                float v0 = acc[nt][half * 2] + b0;
                float v1 = acc[nt][half * 2 + 1] + b1;
                if (col < 128) {
                    float2 o; o.x = v0; o.y = v1;
                    *(float2*)(g_h + (size_t)node * DIM + col) = o;
                } else {
                    int j = col - 128;        // even: 0,2,4,6
                    if (j < 4) {
                        g_asrc[node * NHEADS + j] = v0;
                        g_asrc[node * NHEADS + j + 1] = v1;
                    } else {
                        g_adst[node * NHEADS + j - 4] = v0;
                        g_adst[node * NHEADS + j - 3] = v1;
                    }
                }
            }
        }
        __syncthreads();
    }
}

// ---------------- K2: exp(logits) + dst histogram + sum ----------------
__global__ void logits_hist_kernel(const int* __restrict__ ei) {
    const int* src = ei;
    const int* dst = ei + NEDGES;
    float s0 = 0.f, s1 = 0.f, s2 = 0.f, s3 = 0.f;
    int stride = gridDim.x * blockDim.x;
    for (int e = blockIdx.x * blockDim.x + threadIdx.x; e < NEDGES; e += stride) {
        int s = src[e], d = dst[e];
        atomicAdd(&g_cnt[d], 1);
        float4 as = *(const float4*)(g_asrc + (size_t)s * 4);
        float4 ad = *(const float4*)(g_adst + (size_t)d * 4);
        float4 l;
        l.x = __expf(as.x + ad.x); l.y = __expf(as.y + ad.y);
        l.z = __expf(as.z + ad.z); l.w = __expf(as.w + ad.w);
        *(float4*)(g_exp + (size_t)e * 4) = l;
        s0 += l.x; s1 += l.y; s2 += l.z; s3 += l.w;
    }
    __shared__ float red[4][8];
    int lane = threadIdx.x & 31, w = threadIdx.x >> 5;
#pragma unroll
    for (int o = 16; o; o >>= 1) {
        s0 += __shfl_down_sync(0xffffffffu, s0, o);
        s1 += __shfl_down_sync(0xffffffffu, s1, o);
        s2 += __shfl_down_sync(0xffffffffu, s2, o);
        s3 += __shfl_down_sync(0xffffffffu, s3, o);
    }
    if (lane == 0) { red[0][w] = s0; red[1][w] = s1; red[2][w] = s2; red[3][w] = s3; }
    __syncthreads();
    if (threadIdx.x < 4) {
        float ss = 0.f;
#pragma unroll
        for (int i = 0; i < 8; i++) ss += red[threadIdx.x][i];
        atomicAdd(&g_sum[threadIdx.x], ss);
    }
}

// ---------------- K4a/b: two-level exclusive scan ----------------
__global__ void scan1_kernel() {
    __shared__ int sd[256];
    int t = threadIdx.x;
    int idx = blockIdx.x * 256 + t;
    int v = (idx < NNODES) ? g_cnt[idx] : 0;
    sd[t] = v; __syncthreads();
#pragma unroll
    for (int off = 1; off < 256; off <<= 1) {
        int x = (t >= off) ? sd[t - off] : 0;
        __syncthreads();
        sd[t] += x;
        __syncthreads();
    }
    if (idx < NNODES) g_base[idx] = sd[t] - v;
    if (t == 255) g_part[blockIdx.x] = sd[255];
}
__global__ void scan2_kernel() {
    if (threadIdx.x < NHEADS) g_inv[threadIdx.x] = 1.0f / g_sum[threadIdx.x];
    __shared__ int sd[512];
    int t = threadIdx.x;
    int v = (t < SCAN_B) ? g_part[t] : 0;
    sd[t] = v; __syncthreads();
#pragma unroll
    for (int off = 1; off < 512; off <<= 1) {
        int x = (t >= off) ? sd[t - off] : 0;
        __syncthreads();
        sd[t] += x;
        __syncthreads();
    }
    if (t < SCAN_B) g_poff[t] = sd[t] - v;
    if (t == SCAN_B - 1) g_base[NNODES] = NEDGES - (sd[t] - v);
}

// ---------------- K5: place edges into dst-sorted order (pure permutation) ----
__global__ void place_kernel(const int* __restrict__ ei) {
    const int* src = ei;
    const int* dst = ei + NEDGES;
    int stride = gridDim.x * blockDim.x;
    for (int e = blockIdx.x * blockDim.x + threadIdx.x; e < NEDGES; e += stride) {
        int d = dst[e];
        int pos = g_base[d] + g_poff[d >> 8] + atomicAdd(&g_cnt2[d], 1);
        g_esrc[pos] = src[e];
        g_ea[pos] = *(const float4*)(g_exp + (size_t)e * 4);
    }
}

// ---------------- K6: warp-per-dst aggregation, out = h + inv*agg ----------------
__global__ void agg_kernel(float* __restrict__ out) {
    int lane = threadIdx.x & 31;
    int w = (blockIdx.x * blockDim.x + threadIdx.x) >> 5;
    int nw = (gridDim.x * blockDim.x) >> 5;
    float i0 = g_inv[0], i1 = g_inv[1], i2 = g_inv[2], i3 = g_inv[3];
    for (int d = w; d < NNODES; d += nw) {
        int beg = g_base[d] + g_poff[d >> 8];
        int end = g_base[d + 1] + g_poff[(d + 1) >> 8];
        float a0 = 0.f, a1 = 0.f, a2 = 0.f, a3 = 0.f;
        int p = beg;
        for (; p + 4 <= end; p += 4) {
            int s0 = g_esrc[p], s1 = g_esrc[p + 1], s2 = g_esrc[p + 2], s3 = g_esrc[p + 3];
            float4 w0 = g_ea[p], w1 = g_ea[p + 1], w2 = g_ea[p + 2], w3 = g_ea[p + 3];
            float v0 = g_h[(size_t)s0 * DIM + lane];
            float v1 = g_h[(size_t)s1 * DIM + lane];
            float v2 = g_h[(size_t)s2 * DIM + lane];
            float v3 = g_h[(size_t)s3 * DIM + lane];
            a0 = fmaf(w0.x, v0, fmaf(w1.x, v1, fmaf(w2.x, v2, fmaf(w3.x, v3, a0))));
            a1 = fmaf(w0.y, v0, fmaf(w1.y, v1, fmaf(w2.y, v2, fmaf(w3.y, v3, a1))));
            a2 = fmaf(w0.z, v0, fmaf(w1.z, v1, fmaf(w2.z, v2, fmaf(w3.z, v3, a2))));
            a3 = fmaf(w0.w, v0, fmaf(w1.w, v1, fmaf(w2.w, v2, fmaf(w3.w, v3, a3))));
        }
        for (; p < end; p++) {
            int s = g_esrc[p];
            float4 a = g_ea[p];
            float sv = g_h[(size_t)s * DIM + lane];
            a0 = fmaf(a.x, sv, a0);
            a1 = fmaf(a.y, sv, a1);
            a2 = fmaf(a.z, sv, a2);
            a3 = fmaf(a.w, sv, a3);
        }
        const float* hr = g_h + (size_t)d * DIM;
        float* o = out + (size_t)d * DIM;
        o[lane]      = hr[lane]      + a0 * i0;
        o[32 + lane] = hr[32 + lane] + a1 * i1;
        o[64 + lane] = hr[64 + lane] + a2 * i2;
        o[96 + lane] = hr[96 + lane] + a3 * i3;
    }
}

// ---------------- launch ----------------
extern "C" void kernel_launch(void* const* d_in, const int* in_sizes, int n_in,
                              void* d_out, int out_size) {
    const float* feat = (const float*)d_in[0];
    const int*   ei   = (const int*)d_in[1];
    const float* Wlin = (const float*)d_in[2];
    const float* blin = (const float*)d_in[3];
    const float* Watt = (const float*)d_in[4];
    const float* batt = (const float*)d_in[5];
    float* out = (float*)d_out;

    prep_kernel<<<(NNODES + 1023) / 1024, 1024>>>(Wlin, blin, Watt, batt);
    splitB_kernel<<<(144 * 16 + 255) / 256, 256>>>(Wlin, blin);

    size_t smem = (size_t)(2 * 128 * 128 + 2 * 72 * 128) * sizeof(__nv_bfloat16)
                + 72 * sizeof(float);
    cudaFuncSetAttribute(gemm_kernel, cudaFuncAttributeMaxDynamicSharedMemorySize, (int)smem);
    gemm_kernel<<<296, 256, smem>>>(feat);

    logits_hist_kernel<<<1184, 256>>>(ei);
    scan1_kernel<<<SCAN_B, 256>>>();
    scan2_kernel<<<1, 512>>>();
    place_kernel<<<1184, 256>>>(ei);
    agg_kernel<<<1480, 256>>>(out);
}

// round 14
// speedup vs baseline: 1.0499x; 1.0074x over previous
#include <cuda_runtime.h>
#include <cuda_bf16.h>
#include <cstdint>

#define NNODES 100000
#define NEDGES 500000
#define DIM 128
#define NHEADS 4
#define NTILES ((NNODES + 127) / 128)      // 782
#define SCAN_B ((NNODES + 255) / 256)      // 391

// ---------------- scratch ----------------
__device__ float  g_h[NNODES * DIM];           // 51.2 MB (L2-resident)
__device__ float  g_asrc[NNODES * NHEADS];
__device__ float  g_adst[NNODES * NHEADS];
__device__ float  g_exp[NEDGES * NHEADS];      // unnormalized exp(logit), 8 MB
__device__ float  g_va[8 * DIM];               // wa @ W (4 src rows, 4 dst rows)
__device__ float  g_vc[8];                     // b·wa (+ba for dst part)
__device__ float  g_sum[NHEADS];
// pre-split, pre-swizzled B operand (144 rows x 128 cols bf16, hi+lo) + fused bias
__device__ __nv_bfloat16 g_Bhi[144 * 128];
__device__ __nv_bfloat16 g_Blo[144 * 128];
__device__ float  g_bias[144];
// counting-sort scratch
__device__ int    g_cnt[NNODES];
__device__ int    g_cnt2[NNODES];
__device__ int    g_base[NNODES + 1];
__device__ int    g_part[SCAN_B];
__device__ int    g_poff[SCAN_B];
__device__ int    g_esrc[NEDGES];
__device__ float4 g_ea[NEDGES];                // unnormalized exp per sorted slot

// ---------------- side stream + fork/join events (static init, pre-checkpoint) --
namespace {
struct StreamInit {
    cudaStream_t s2 = nullptr;
    cudaEvent_t evA = nullptr, evB = nullptr;
    StreamInit() {
        cudaStreamCreateWithFlags(&s2, cudaStreamNonBlocking);
        cudaEventCreateWithFlags(&evA, cudaEventDisableTiming);
        cudaEventCreateWithFlags(&evB, cudaEventDisableTiming);
    }
};
StreamInit g_si;
}

// ---------------- helpers ----------------
__device__ __forceinline__ uint32_t smaddr(const void* p) {
    return (uint32_t)__cvta_generic_to_shared(p);
}
__device__ __forceinline__ void split2(float v0, float v1, uint32_t& hp, uint32_t& lp) {
    asm("cvt.rn.bf16x2.f32 %0, %1, %2;" : "=r"(hp) : "f"(v1), "f"(v0));
    float h0 = __uint_as_float(hp << 16);
    float h1 = __uint_as_float(hp & 0xffff0000u);
    asm("cvt.rn.bf16x2.f32 %0, %1, %2;" : "=r"(lp) : "f"(v1 - h1), "f"(v0 - h0));
}
__device__ __forceinline__ int swz(int row, int ch) {
    return row * 128 + ((ch ^ (row & 7)) << 3);
}
__device__ __forceinline__ float frcp(float x) {
    float r;
    asm("rcp.approx.f32 %0, %1;" : "=f"(r) : "f"(x));
    return r;
}

#define LDSM4(r0, r1, r2, r3, addr) \
    asm volatile("ldmatrix.sync.aligned.m8n8.x4.shared.b16 {%0,%1,%2,%3}, [%4];" \
                 : "=r"(r0), "=r"(r1), "=r"(r2), "=r"(r3) : "r"(addr))
#define MMA16816(d, a, b0, b1) \
    asm volatile("mma.sync.aligned.m16n8k16.row.col.f32.bf16.bf16.f32 " \
                 "{%0,%1,%2,%3}, {%4,%5,%6,%7}, {%8,%9}, {%0,%1,%2,%3};" \
                 : "+f"(d[0]), "+f"(d[1]), "+f"(d[2]), "+f"(d[3]) \
                 : "r"(a[0]), "r"(a[1]), "r"(a[2]), "r"(a[3]), "r"(b0), "r"(b1))

// ---------------- K0: zero counters + va (fused) ----------------
__global__ void prep_kernel(const float* __restrict__ W,
                            const float* __restrict__ b,
                            const float* __restrict__ Wa,
                            const float* __restrict__ ba) {
    int i = blockIdx.x * blockDim.x + threadIdx.x;
    if (i < NNODES) { g_cnt[i] = 0; g_cnt2[i] = 0; }
    if (i < NHEADS) g_sum[i] = 0.0f;
    if (blockIdx.x == 0) {      // 1024 threads: va = wa @ W
        int t = threadIdx.x;
        int j = t >> 7, ii = t & 127;
        int head = j & 3, part = j >> 2;
        const float* war = Wa + head * 2 * DIM + part * DIM;
        float s = 0.f;
        for (int k = 0; k < DIM; k++) s += war[k] * W[k * DIM + ii];
        g_va[j * DIM + ii] = s;
        if (t < 8) {
            int hh = t & 3, pp = t >> 2;
            const float* wr = Wa + hh * 2 * DIM + pp * DIM;
            float c = 0.f;
            for (int k = 0; k < DIM; k++) c += b[k] * wr[k];
            if (pp) c += ba[hh];
            g_vc[t] = c;
        }
    }
}

// ---------------- K0c: pre-split + pre-swizzle B, fuse bias ----------------
__global__ void splitB_kernel(const float* __restrict__ W,
                              const float* __restrict__ b) {
    int idx = blockIdx.x * blockDim.x + threadIdx.x;   // 144*16 items
    if (idx >= 144 * 16) return;
    int row = idx >> 4, ch = idx & 15;
    float v[8];
    if (row < 128) {
        const float4* p = (const float4*)(W + row * 128 + ch * 8);
        float4 a = p[0], c = p[1];
        v[0] = a.x; v[1] = a.y; v[2] = a.z; v[3] = a.w;
        v[4] = c.x; v[5] = c.y; v[6] = c.z; v[7] = c.w;
    } else if (row < 136) {
        const float4* p = (const float4*)(g_va + (row - 128) * 128 + ch * 8);
        float4 a = p[0], c = p[1];
        v[0] = a.x; v[1] = a.y; v[2] = a.z; v[3] = a.w;
        v[4] = c.x; v[5] = c.y; v[6] = c.z; v[7] = c.w;
    } else {
#pragma unroll
        for (int i = 0; i < 8; i++) v[i] = 0.f;
    }
    uint32_t uh[4], ul[4];
#pragma unroll
    for (int i = 0; i < 4; i++) split2(v[2 * i], v[2 * i + 1], uh[i], ul[i]);
    int off = swz(row, ch);
    *(uint4*)(g_Bhi + off) = make_uint4(uh[0], uh[1], uh[2], uh[3]);
    *(uint4*)(g_Blo + off) = make_uint4(ul[0], ul[1], ul[2], ul[3]);
    if (idx < 144)
        g_bias[idx] = (idx < 128) ? b[idx] : (idx < 136 ? g_vc[idx - 128] : 0.f);
}

// ---------------- K1: persistent split-bf16 tensor-core GEMM ----------------
__global__ void __launch_bounds__(256, 2)
gemm_kernel(const float* __restrict__ feat) {
    extern __shared__ char smraw[];
    __nv_bfloat16* Ahi = (__nv_bfloat16*)smraw;          // 128*128 (32KB)
    __nv_bfloat16* Alo = Ahi + 128 * 128;                // 32KB
    __nv_bfloat16* Bhi = Alo + 128 * 128;                // 72*128 (18KB)
    __nv_bfloat16* Blo = Bhi + 72 * 128;                 // 18KB
    float* sbias = (float*)(Blo + 72 * 128);             // 72

    int tid = threadIdx.x;
    int ny = blockIdx.x & 1;
    int col_base = ny * 72;

    {
        const uint4* srcH = (const uint4*)(g_Bhi + col_base * 128);
        const uint4* srcL = (const uint4*)(g_Blo + col_base * 128);
        for (int i = tid; i < 72 * 128 / 8; i += 256) {
            ((uint4*)Bhi)[i] = srcH[i];
            ((uint4*)Blo)[i] = srcL[i];
        }
        for (int i = tid; i < 72; i += 256) sbias[i] = g_bias[col_base + i];
    }

    int warp = tid >> 5, lane = tid & 31;
    int tq = lane >> 2, tr = lane & 3;

    for (int tile = blockIdx.x >> 1; tile < NTILES; tile += gridDim.x >> 1) {
        int nb = tile * 128;

        for (int idx = tid; idx < 128 * 16; idx += 256) {
            int row = idx >> 4, ch = idx & 15;
            int node = nb + row;
            float v[8];
            if (node < NNODES) {
                const float4* p = (const float4*)(feat + (size_t)node * 128 + ch * 8);
                float4 a = p[0], c = p[1];
                v[0] = a.x; v[1] = a.y; v[2] = a.z; v[3] = a.w;
                v[4] = c.x; v[5] = c.y; v[6] = c.z; v[7] = c.w;
            } else {
#pragma unroll
                for (int i = 0; i < 8; i++) v[i] = 0.f;
            }
            uint32_t uh[4], ul[4];
#pragma unroll
            for (int i = 0; i < 4; i++) split2(v[2 * i], v[2 * i + 1], uh[i], ul[i]);
            int off = swz(row, ch);
            *(uint4*)(Ahi + off) = make_uint4(uh[0], uh[1], uh[2], uh[3]);
            *(uint4*)(Alo + off) = make_uint4(ul[0], ul[1], ul[2], ul[3]);
        }
        __syncthreads();

        float acc[9][4];
#pragma unroll
        for (int nt = 0; nt < 9; nt++)
#pragma unroll
            for (int i = 0; i < 4; i++) acc[nt][i] = 0.f;

        for (int ks = 0; ks < 8; ks++) {
            uint32_t ah[4], al[4];
            {
                int row = warp * 16 + (lane & 15);
                int ch = ks * 2 + (lane >> 4);
                uint32_t ad = smaddr(Ahi + swz(row, ch));
                LDSM4(ah[0], ah[1], ah[2], ah[3], ad);
                uint32_t ad2 = smaddr(Alo + swz(row, ch));
                LDSM4(al[0], al[1], al[2], al[3], ad2);
            }
            int rowb_pair = (lane & 7) + ((lane >> 4) << 3);
            int chb = ks * 2 + ((lane >> 3) & 1);

            uint32_t bh[4][4], bl[4][4], bh8[2], bl8[2];
#pragma unroll
            for (int np = 0; np < 4; np++) {
                int rb = np * 16 + rowb_pair;
                uint32_t bd = smaddr(Bhi + swz(rb, chb));
                LDSM4(bh[np][0], bh[np][1], bh[np][2], bh[np][3], bd);
                uint32_t bd2 = smaddr(Blo + swz(rb, chb));
                LDSM4(bl[np][0], bl[np][1], bl[np][2], bl[np][3], bd2);
            }
            {
                int rb = 64 + (lane & 7);
                const __nv_bfloat16* Bt = (lane & 16) ? Blo : Bhi;
                uint32_t bd = smaddr(Bt + swz(rb, chb));
                LDSM4(bh8[0], bh8[1], bl8[0], bl8[1], bd);
            }

#pragma unroll
            for (int np = 0; np < 4; np++) {
                MMA16816(acc[2 * np],     ah, bh[np][0], bh[np][1]);
                MMA16816(acc[2 * np + 1], ah, bh[np][2], bh[np][3]);
            }
            MMA16816(acc[8], ah, bh8[0], bh8[1]);
#pragma unroll
            for (int np = 0; np < 4; np++) {
                MMA16816(acc[2 * np],     ah, bl[np][0], bl[np][1]);
                MMA16816(acc[2 * np + 1], ah, bl[np][2], bl[np][3]);
            }
            MMA16816(acc[8], ah, bl8[0], bl8[1]);
#pragma unroll
            for (int np = 0; np < 4; np++) {
                MMA16816(acc[2 * np],     al, bh[np][0], bh[np][1]);
                MMA16816(acc[2 * np + 1], al, bh[np][2], bh[np][3]);
            }
            MMA16816(acc[8], al, bh8[0], bh8[1]);
        }

#pragma unroll
        for (int nt = 0; nt < 9; nt++) {
            int col = col_base + nt * 8 + tr * 2;
            if (col >= 136) continue;
            float b0 = sbias[nt * 8 + tr * 2], b1 = sbias[nt * 8 + tr * 2 + 1];
#pragma unroll
            for (int half = 0; half < 2; half++) {
                int node = nb + warp * 16 + tq + half * 8;
                if (node >= NNODES) continue;
                float v0 = acc[nt][half * 2] + b0;
                float v1 = acc[nt][half * 2 + 1] + b1;
                if (col < 128) {
                    float2 o; o.x = v0; o.y = v1;
                    *(float2*)(g_h + (size_t)node * DIM + col) = o;
                } else {
                    int j = col - 128;
                    if (j < 4) {
                        g_asrc[node * NHEADS + j] = v0;
                        g_asrc[node * NHEADS + j + 1] = v1;
                    } else {
                        g_adst[node * NHEADS + j - 4] = v0;
                        g_adst[node * NHEADS + j - 3] = v1;
                    }
                }
            }
        }
        __syncthreads();
    }
}

// ---------------- K2a (side stream): dst histogram only ----------------
__global__ void hist_kernel(const int* __restrict__ ei) {
    const int* dst = ei + NEDGES;
    int stride = gridDim.x * blockDim.x;
    for (int e = blockIdx.x * blockDim.x + threadIdx.x; e < NEDGES; e += stride)
        atomicAdd(&g_cnt[dst[e]], 1);
}

// ---------------- K2b: exp(logits) + sum (no histogram) ----------------
__global__ void logits_kernel(const int* __restrict__ ei) {
    const int* src = ei;
    const int* dst = ei + NEDGES;
    float s0 = 0.f, s1 = 0.f, s2 = 0.f, s3 = 0.f;
    int stride = gridDim.x * blockDim.x;
    for (int e = blockIdx.x * blockDim.x + threadIdx.x; e < NEDGES; e += stride) {
        int s = src[e], d = dst[e];
        float4 as = *(const float4*)(g_asrc + (size_t)s * 4);
        float4 ad = *(const float4*)(g_adst + (size_t)d * 4);
        float4 l;
        l.x = __expf(as.x + ad.x); l.y = __expf(as.y + ad.y);
        l.z = __expf(as.z + ad.z); l.w = __expf(as.w + ad.w);
        *(float4*)(g_exp + (size_t)e * 4) = l;
        s0 += l.x; s1 += l.y; s2 += l.z; s3 += l.w;
    }
    __shared__ float red[4][8];
    int lane = threadIdx.x & 31, w = threadIdx.x >> 5;
#pragma unroll
    for (int o = 16; o; o >>= 1) {
        s0 += __shfl_down_sync(0xffffffffu, s0, o);
        s1 += __shfl_down_sync(0xffffffffu, s1, o);
        s2 += __shfl_down_sync(0xffffffffu, s2, o);
        s3 += __shfl_down_sync(0xffffffffu, s3, o);
    }
    if (lane == 0) { red[0][w] = s0; red[1][w] = s1; red[2][w] = s2; red[3][w] = s3; }
    __syncthreads();
    if (threadIdx.x < 4) {
        float ss = 0.f;
#pragma unroll
        for (int i = 0; i < 8; i++) ss += red[threadIdx.x][i];
        atomicAdd(&g_sum[threadIdx.x], ss);
    }
}

// ---------------- K4a/b: two-level exclusive scan (side stream) ----------------
__global__ void scan1_kernel() {
    __shared__ int sd[256];
    int t = threadIdx.x;
    int idx = blockIdx.x * 256 + t;
    int v = (idx < NNODES) ? g_cnt[idx] : 0;
    sd[t] = v; __syncthreads();
#pragma unroll
    for (int off = 1; off < 256; off <<= 1) {
        int x = (t >= off) ? sd[t - off] : 0;
        __syncthreads();
        sd[t] += x;
        __syncthreads();
    }
    if (idx < NNODES) g_base[idx] = sd[t] - v;
    if (t == 255) g_part[blockIdx.x] = sd[255];
}
__global__ void scan2_kernel() {
    __shared__ int sd[512];
    int t = threadIdx.x;
    int v = (t < SCAN_B) ? g_part[t] : 0;
    sd[t] = v; __syncthreads();
#pragma unroll
    for (int off = 1; off < 512; off <<= 1) {
        int x = (t >= off) ? sd[t - off] : 0;
        __syncthreads();
        sd[t] += x;
        __syncthreads();
    }
    if (t < SCAN_B) g_poff[t] = sd[t] - v;
    if (t == SCAN_B - 1) g_base[NNODES] = NEDGES - (sd[t] - v);
}

// ---------------- K5: place edges into dst-sorted order (pure permutation) ----
__global__ void place_kernel(const int* __restrict__ ei) {
    const int* src = ei;
    const int* dst = ei + NEDGES;
    int stride = gridDim.x * blockDim.x;
    for (int e = blockIdx.x * blockDim.x + threadIdx.x; e < NEDGES; e += stride) {
        int d = dst[e];
        int pos = g_base[d] + g_poff[d >> 8] + atomicAdd(&g_cnt2[d], 1);
        g_esrc[pos] = src[e];
        g_ea[pos] = *(const float4*)(g_exp + (size_t)e * 4);
    }
}

// ---------------- K6: warp-per-dst aggregation, out = h + inv*agg ----------------
__global__ void agg_kernel(float* __restrict__ out) {
    int lane = threadIdx.x & 31;
    int w = (blockIdx.x * blockDim.x + threadIdx.x) >> 5;
    int nw = (gridDim.x * blockDim.x) >> 5;
    float i0 = frcp(g_sum[0]), i1 = frcp(g_sum[1]);
    float i2 = frcp(g_sum[2]), i3 = frcp(g_sum[3]);
    for (int d = w; d < NNODES; d += nw) {
        int beg = g_base[d] + g_poff[d >> 8];
        int end = g_base[d + 1] + g_poff[(d + 1) >> 8];
        float a0 = 0.f, a1 = 0.f, a2 = 0.f, a3 = 0.f;
        int p = beg;
        for (; p + 4 <= end; p += 4) {
            int s0 = g_esrc[p], s1 = g_esrc[p + 1], s2 = g_esrc[p + 2], s3 = g_esrc[p + 3];
            float4 w0 = g_ea[p], w1 = g_ea[p + 1], w2 = g_ea[p + 2], w3 = g_ea[p + 3];
            float v0 = g_h[(size_t)s0 * DIM + lane];
            float v1 = g_h[(size_t)s1 * DIM + lane];
            float v2 = g_h[(size_t)s2 * DIM + lane];
            float v3 = g_h[(size_t)s3 * DIM + lane];
            a0 = fmaf(w0.x, v0, fmaf(w1.x, v1, fmaf(w2.x, v2, fmaf(w3.x, v3, a0))));
            a1 = fmaf(w0.y, v0, fmaf(w1.y, v1, fmaf(w2.y, v2, fmaf(w3.y, v3, a1))));
            a2 = fmaf(w0.z, v0, fmaf(w1.z, v1, fmaf(w2.z, v2, fmaf(w3.z, v3, a2))));
            a3 = fmaf(w0.w, v0, fmaf(w1.w, v1, fmaf(w2.w, v2, fmaf(w3.w, v3, a3))));
        }
        for (; p < end; p++) {
            int s = g_esrc[p];
            float4 a = g_ea[p];
            float sv = g_h[(size_t)s * DIM + lane];
            a0 = fmaf(a.x, sv, a0);
            a1 = fmaf(a.y, sv, a1);
            a2 = fmaf(a.z, sv, a2);
            a3 = fmaf(a.w, sv, a3);
        }
        const float* hr = g_h + (size_t)d * DIM;
        float* o = out + (size_t)d * DIM;
        o[lane]      = hr[lane]      + a0 * i0;
        o[32 + lane] = hr[32 + lane] + a1 * i1;
        o[64 + lane] = hr[64 + lane] + a2 * i2;
        o[96 + lane] = hr[96 + lane] + a3 * i3;
    }
}

// ---------------- launch ----------------
extern "C" void kernel_launch(void* const* d_in, const int* in_sizes, int n_in,
                              void* d_out, int out_size) {
    const float* feat = (const float*)d_in[0];
    const int*   ei   = (const int*)d_in[1];
    const float* Wlin = (const float*)d_in[2];
    const float* blin = (const float*)d_in[3];
    const float* Watt = (const float*)d_in[4];
    const float* batt = (const float*)d_in[5];
    float* out = (float*)d_out;

    prep_kernel<<<(NNODES + 1023) / 1024, 1024>>>(Wlin, blin, Watt, batt);

    // fork: histogram + scans on side stream, overlapped with GEMM chain
    cudaEventRecord(g_si.evA, 0);
    cudaStreamWaitEvent(g_si.s2, g_si.evA, 0);
    hist_kernel<<<592, 256, 0, g_si.s2>>>(ei);
    scan1_kernel<<<SCAN_B, 256, 0, g_si.s2>>>();
    scan2_kernel<<<1, 512, 0, g_si.s2>>>();
    cudaEventRecord(g_si.evB, g_si.s2);

    // main chain
    splitB_kernel<<<(144 * 16 + 255) / 256, 256>>>(Wlin, blin);
    size_t smem = (size_t)(2 * 128 * 128 + 2 * 72 * 128) * sizeof(__nv_bfloat16)
                + 72 * sizeof(float);
    cudaFuncSetAttribute(gemm_kernel, cudaFuncAttributeMaxDynamicSharedMemorySize, (int)smem);
    gemm_kernel<<<296, 256, smem>>>(feat);
    logits_kernel<<<1184, 256>>>(ei);

    // join
    cudaStreamWaitEvent(0, g_si.evB, 0);
    place_kernel<<<1184, 256>>>(ei);
    agg_kernel<<<1480, 256>>>(out);
}